// round 17
// baseline (speedup 1.0000x reference)
#include <cuda_runtime.h>
#include <cuda_fp16.h>
#include <cstdint>

// Problem constants
#define BATCH  2
#define SEQ    2048
#define DIN    64
#define NHEAD  16
#define DHEAD  64
#define HB     32
#define HD     1024
#define NROWS  4096
#define DO     1024

#define ATTN_ELEMS 134217728LL
#define OUT_ELEMS  4194304LL

// fold 1/sqrt(64) and log2(e): scores kept in log2 domain
#define SCL (0.125f * 1.4426950408889634f)

// -------------------- scratch --------------------
__device__ __half g_QHh[HB * SEQ * DHEAD];   // Q scaled by SCL, f16 hi
__device__ __half g_QLh[HB * SEQ * DHEAD];   // f16 lo
__device__ __half g_KHh[HB * SEQ * DHEAD];
__device__ __half g_KLh[HB * SEQ * DHEAD];
__device__ __half g_VHh[HB * SEQ * DHEAD];
__device__ __half g_VLh[HB * SEQ * DHEAD];
__device__ float g_m[HB * SEQ];
__device__ float g_l[HB * SEQ];
__device__ float g_oh[NROWS * HD];
__device__ float g_attn_fb[134217728];

// -------------------- helpers --------------------
__device__ __forceinline__ uint32_t su32(const void* p) {
    uint32_t a;
    asm("{ .reg .u64 t; cvta.to.shared.u64 t, %1; cvt.u32.u64 %0, t; }" : "=r"(a) : "l"(p));
    return a;
}
__device__ __forceinline__ float ex2f(float x) {
    float y;
    asm("ex2.approx.f32 %0, %1;" : "=f"(y) : "f"(x));
    return y;
}
__device__ __forceinline__ void h2split(float4 v, uint2& hp, uint2& lp) {
    __half2 h0 = __floats2half2_rn(v.x, v.y);
    __half2 h1 = __floats2half2_rn(v.z, v.w);
    float2 f0 = __half22float2(h0), f1 = __half22float2(h1);
    __half2 l0 = __floats2half2_rn(v.x - f0.x, v.y - f0.y);
    __half2 l1 = __floats2half2_rn(v.z - f1.x, v.w - f1.y);
    hp.x = *(uint32_t*)&h0; hp.y = *(uint32_t*)&h1;
    lp.x = *(uint32_t*)&l0; lp.y = *(uint32_t*)&l1;
}
__device__ __forceinline__ uint2 h2hi(float4 v) {
    __half2 h0 = __floats2half2_rn(v.x, v.y);
    __half2 h1 = __floats2half2_rn(v.z, v.w);
    uint2 hp;
    hp.x = *(uint32_t*)&h0; hp.y = *(uint32_t*)&h1;
    return hp;
}
__device__ __forceinline__ void mma_f16(float* c, const uint32_t* a, const uint32_t* b) {
    asm volatile("mma.sync.aligned.m16n8k16.row.col.f32.f16.f16.f32 "
                 "{%0,%1,%2,%3}, {%4,%5,%6,%7}, {%8,%9}, {%0,%1,%2,%3};"
                 : "+f"(c[0]), "+f"(c[1]), "+f"(c[2]), "+f"(c[3])
                 : "r"(a[0]), "r"(a[1]), "r"(a[2]), "r"(a[3]), "r"(b[0]), "r"(b[1]));
}
__device__ __forceinline__ void ldmA(uint32_t* r, uint32_t addr) {
    asm volatile("ldmatrix.sync.aligned.m8n8.x4.shared.b16 {%0,%1,%2,%3}, [%4];"
                 : "=r"(r[0]), "=r"(r[1]), "=r"(r[2]), "=r"(r[3]) : "r"(addr));
}
__device__ __forceinline__ void ldmB4(uint32_t* r, uint32_t addr) {
    asm volatile("ldmatrix.sync.aligned.m8n8.x4.trans.shared.b16 {%0,%1,%2,%3}, [%4];"
                 : "=r"(r[0]), "=r"(r[1]), "=r"(r[2]), "=r"(r[3]) : "r"(addr));
}
__device__ __forceinline__ void ldmBn4(uint32_t* r, uint32_t addr) {
    asm volatile("ldmatrix.sync.aligned.m8n8.x4.shared.b16 {%0,%1,%2,%3}, [%4];"
                 : "=r"(r[0]), "=r"(r[1]), "=r"(r[2]), "=r"(r[3]) : "r"(addr));
}
#define CP16(smem_addr, gptr) \
    asm volatile("cp.async.ca.shared.global [%0], [%1], 16;" :: "r"(smem_addr), "l"(gptr))
#define CP_COMMIT() asm volatile("cp.async.commit_group;" ::: "memory")
#define CP_WAIT0()  asm volatile("cp.async.wait_group 0;" ::: "memory")

// ==================== kernel 1: fused QKV projections (writes f16 hi/lo splits) ====================
__global__ __launch_bounds__(256) void proj_fused_kernel(
    const float* __restrict__ q, const float* __restrict__ k, const float* __restrict__ v,
    const float* __restrict__ Wq, const float* __restrict__ bq,
    const float* __restrict__ Wk, const float* __restrict__ bk,
    const float* __restrict__ Wv, const float* __restrict__ bv,
    __half* __restrict__ QH, __half* __restrict__ QL,
    __half* __restrict__ KH, __half* __restrict__ KL,
    __half* __restrict__ VH, __half* __restrict__ VL) {
    __shared__ float Xs[64][65];
    __shared__ float Ws[64][65];
    int rt = blockIdx.x, head = blockIdx.y, z = blockIdx.z, tid = threadIdx.x;
    const float* X = (z == 0) ? q : (z == 1) ? k : v;
    const float* W = (z == 0) ? Wq : (z == 1) ? Wk : Wv;
    const float* bias = (z == 0) ? bq : (z == 1) ? bk : bv;
    __half* OutH = (z == 0) ? QH : (z == 1) ? KH : VH;
    __half* OutL = (z == 0) ? QL : (z == 1) ? KL : VL;

#pragma unroll
    for (int t = 0; t < 4; t++) {
        int f = tid + t * 256;
        int r = f >> 4, c = (f & 15) << 2;
        float4 xv = *(const float4*)(X + (size_t)(rt * 64 + r) * DIN + c);
        Xs[r][c] = xv.x; Xs[r][c + 1] = xv.y; Xs[r][c + 2] = xv.z; Xs[r][c + 3] = xv.w;
        float4 wv = *(const float4*)(W + (size_t)r * HD + head * 64 + c);
        Ws[r][c] = wv.x; Ws[r][c + 1] = wv.y; Ws[r][c + 2] = wv.z; Ws[r][c + 3] = wv.w;
    }
    __syncthreads();
    int ty = tid >> 4, tx = tid & 15;
    int r0 = ty * 4, c0 = tx * 4;
    float acc[4][4] = {};
#pragma unroll
    for (int kk = 0; kk < 64; kk++) {
        float a[4], b[4];
#pragma unroll
        for (int i = 0; i < 4; i++) a[i] = Xs[r0 + i][kk];
#pragma unroll
        for (int j = 0; j < 4; j++) b[j] = Ws[kk][c0 + j];
#pragma unroll
        for (int i = 0; i < 4; i++)
#pragma unroll
            for (int j = 0; j < 4; j++) acc[i][j] = fmaf(a[i], b[j], acc[i][j]);
    }
    int bb = (rt * 64) / SEQ;
    int nbase = rt * 64 - bb * SEQ;
    float bv4[4];
#pragma unroll
    for (int j = 0; j < 4; j++) bv4[j] = bias[head * 64 + c0 + j];
    float scl = (z == 0) ? SCL : 1.0f;
#pragma unroll
    for (int i = 0; i < 4; i++) {
        float4 o;
        o.x = (acc[i][0] + bv4[0]) * scl; o.y = (acc[i][1] + bv4[1]) * scl;
        o.z = (acc[i][2] + bv4[2]) * scl; o.w = (acc[i][3] + bv4[3]) * scl;
        size_t row = (size_t)(head * BATCH + bb) * SEQ + nbase + r0 + i;
        uint2 hp, lp;
        h2split(o, hp, lp);
        *(uint2*)(OutH + row * DHEAD + c0) = hp;
        *(uint2*)(OutL + row * DHEAD + c0) = lp;
    }
}

// ==================== kernel 2: scores via f16-3x m16n8k16 (cp.async staging) ====================
// 512 threads, 16 warps; warp = (wr 0..3 rowgroup of 32, wq 0..3 colquad of 32)
#define SC_QH 0
#define SC_QL 18432
#define SC_KB0 36864
#define SC_KBSTRIDE 36864
#define SC_STATS 110592
#define SC_SMEM_BYTES 114688

__global__ __launch_bounds__(512, 1) void scores_mma_kernel(
    float* __restrict__ attn,
    const __half* __restrict__ QH, const __half* __restrict__ QL,
    const __half* __restrict__ KH, const __half* __restrict__ KL) {
    extern __shared__ char smc[];
    uint32_t sb = su32(smc);

    int tid = threadIdx.x, lane = tid & 31, w = tid >> 5;
    int g = lane >> 2, tg = lane & 3;
    int wr = w & 3, wq = w >> 2;
    int hb = blockIdx.x, qt = blockIdx.y;
    int r1 = wr * 32 + g;

    // staging coordinates: 1024 16B-chunks per 128x64-half tile, 2 per thread
    int sr0 = tid >> 3, sc0 = (tid & 7) * 8;           // rows 0..63
    int sr1 = sr0 + 64;                                 // rows 64..127

    // ---- Q staging via cp.async (pre-split, pre-scaled) ----
    size_t qbase = (size_t)(hb * SEQ + qt * 128);
    CP16(sb + SC_QH + (sr0 * 72 + sc0) * 2, QH + (qbase + sr0) * DHEAD + sc0);
    CP16(sb + SC_QH + (sr1 * 72 + sc0) * 2, QH + (qbase + sr1) * DHEAD + sc0);
    CP16(sb + SC_QL + (sr0 * 72 + sc0) * 2, QL + (qbase + sr0) * DHEAD + sc0);
    CP16(sb + SC_QL + (sr1 * 72 + sc0) * 2, QL + (qbase + sr1) * DHEAD + sc0);
    // ---- K tile 0 -> buf0 ----
    size_t kbase = (size_t)(hb * SEQ);
    {
        uint32_t kb = sb + SC_KB0;
        CP16(kb + (sr0 * 72 + sc0) * 2, KH + (kbase + sr0) * DHEAD + sc0);
        CP16(kb + (sr1 * 72 + sc0) * 2, KH + (kbase + sr1) * DHEAD + sc0);
        CP16(kb + 18432 + (sr0 * 72 + sc0) * 2, KL + (kbase + sr0) * DHEAD + sc0);
        CP16(kb + 18432 + (sr1 * 72 + sc0) * 2, KL + (kbase + sr1) * DHEAD + sc0);
    }
    CP_COMMIT();
    CP_WAIT0();
    __syncthreads();

    float mA[2] = {-1e30f, -1e30f}, lA[2] = {0.f, 0.f};
    float mB[2] = {-1e30f, -1e30f}, lB[2] = {0.f, 0.f};
    float* Tbase = attn + (size_t)hb * SEQ * SEQ + (size_t)(qt * 128) * SEQ;

    int arow = (lane & 15);
    int acl = ((lane >> 4) & 1) * 8;
    int bkey4 = wq * 32 + (lane & 7) + ((lane >> 4) & 1) * 8;
    int bdim4 = ((lane >> 3) & 1) * 8;

    for (int kt = 0; kt < 16; kt++) {
        if (kt < 15) {
            size_t kb2 = kbase + (size_t)(kt + 1) * 128;
            uint32_t kb = sb + SC_KB0 + ((kt + 1) & 1) * SC_KBSTRIDE;
            CP16(kb + (sr0 * 72 + sc0) * 2, KH + (kb2 + sr0) * DHEAD + sc0);
            CP16(kb + (sr1 * 72 + sc0) * 2, KH + (kb2 + sr1) * DHEAD + sc0);
            CP16(kb + 18432 + (sr0 * 72 + sc0) * 2, KL + (kb2 + sr0) * DHEAD + sc0);
            CP16(kb + 18432 + (sr1 * 72 + sc0) * 2, KL + (kb2 + sr1) * DHEAD + sc0);
            CP_COMMIT();
        }
        uint32_t kbH = sb + SC_KB0 + (kt & 1) * SC_KBSTRIDE;
        uint32_t kbL = kbH + 18432;

        float C[2][4][4];
#pragma unroll
        for (int mt = 0; mt < 2; mt++)
#pragma unroll
            for (int j = 0; j < 4; j++) { C[mt][j][0] = C[mt][j][1] = C[mt][j][2] = C[mt][j][3] = 0.f; }

#pragma unroll
        for (int ks = 0; ks < 4; ks++) {
            uint32_t aH[2][4], aL[2][4];
#pragma unroll
            for (int mt = 0; mt < 2; mt++) {
                uint32_t off = (uint32_t)(((wr * 32 + mt * 16 + arow) * 72 + ks * 16 + acl) * 2);
                ldmA(aH[mt], sb + SC_QH + off);
                ldmA(aL[mt], sb + SC_QL + off);
            }
#pragma unroll
            for (int jp = 0; jp < 2; jp++) {
                uint32_t boff = (uint32_t)(((bkey4 + jp * 16) * 72 + ks * 16 + bdim4) * 2);
                uint32_t b4H[4], b4L[4];
                ldmBn4(b4H, kbH + boff);
                ldmBn4(b4L, kbL + boff);
#pragma unroll
                for (int jj = 0; jj < 2; jj++)
#pragma unroll
                    for (int mt = 0; mt < 2; mt++) {
                        float* Cp = C[mt][jp * 2 + jj];
                        mma_f16(Cp, aH[mt], b4H + jj * 2);
                        mma_f16(Cp, aH[mt], b4L + jj * 2);
                        mma_f16(Cp, aL[mt], b4H + jj * 2);
                    }
            }
        }

        // online partial stats over this warp's 32 columns
#pragma unroll
        for (int mt = 0; mt < 2; mt++) {
            float mxa = C[mt][0][0], mxb = C[mt][0][2];
#pragma unroll
            for (int j = 0; j < 4; j++) {
                mxa = fmaxf(mxa, fmaxf(C[mt][j][0], C[mt][j][1]));
                mxb = fmaxf(mxb, fmaxf(C[mt][j][2], C[mt][j][3]));
            }
            mxa = fmaxf(mxa, __shfl_xor_sync(0xffffffffu, mxa, 1));
            mxa = fmaxf(mxa, __shfl_xor_sync(0xffffffffu, mxa, 2));
            mxb = fmaxf(mxb, __shfl_xor_sync(0xffffffffu, mxb, 1));
            mxb = fmaxf(mxb, __shfl_xor_sync(0xffffffffu, mxb, 2));
            float M1 = fmaxf(mA[mt], mxa), M2 = fmaxf(mB[mt], mxb);
            float sa = 0.f, sb2 = 0.f;
#pragma unroll
            for (int j = 0; j < 4; j++) {
                sa  += ex2f(C[mt][j][0] - M1) + ex2f(C[mt][j][1] - M1);
                sb2 += ex2f(C[mt][j][2] - M2) + ex2f(C[mt][j][3] - M2);
            }
            sa  += __shfl_xor_sync(0xffffffffu, sa, 1);
            sa  += __shfl_xor_sync(0xffffffffu, sa, 2);
            sb2 += __shfl_xor_sync(0xffffffffu, sb2, 1);
            sb2 += __shfl_xor_sync(0xffffffffu, sb2, 2);
            lA[mt] = lA[mt] * ex2f(mA[mt] - M1) + sa;  mA[mt] = M1;
            lB[mt] = lB[mt] * ex2f(mB[mt] - M2) + sb2; mB[mt] = M2;
        }

        // store raw log2-domain scores
#pragma unroll
        for (int mt = 0; mt < 2; mt++) {
            int rr = r1 + mt * 16;
            float* p1 = Tbase + (size_t)rr * SEQ + kt * 128 + wq * 32 + 2 * tg;
            float* p2 = p1 + (size_t)8 * SEQ;
#pragma unroll
            for (int j = 0; j < 4; j++) {
                *(float2*)(p1 + j * 8) = make_float2(C[mt][j][0], C[mt][j][1]);
                *(float2*)(p2 + j * 8) = make_float2(C[mt][j][2], C[mt][j][3]);
            }
        }

        if (kt < 15) CP_WAIT0();
        __syncthreads();
    }

    // combine 4 column-quad partials per row
    float* smm = (float*)(smc + SC_STATS);
    float* sml = smm + 512;
    if (tg == 0) {
#pragma unroll
        for (int mt = 0; mt < 2; mt++) {
            int rr = r1 + mt * 16;
            smm[wq * 128 + rr] = mA[mt];      sml[wq * 128 + rr] = lA[mt];
            smm[wq * 128 + rr + 8] = mB[mt];  sml[wq * 128 + rr + 8] = lB[mt];
        }
    }
    __syncthreads();
    if (tid < 128) {
        float M = smm[tid];
#pragma unroll
        for (int qd = 1; qd < 4; qd++) M = fmaxf(M, smm[qd * 128 + tid]);
        float L = 0.f;
#pragma unroll
        for (int qd = 0; qd < 4; qd++) L += sml[qd * 128 + tid] * ex2f(smm[qd * 128 + tid] - M);
        int base = hb * SEQ + qt * 128;
        g_m[base + tid] = M;
        g_l[base + tid] = L;
    }
}

// ==================== kernel 3: normalize + PV, 128-key chunks, cp.async V ====================
// 512 threads; warp = (wr 0..7 rows of 16, wc 0..1 col half of 32)
// buffer: AH 0 (34816 = 128 rows x 136 stride), VH 34816 (18432), VL 53248 (18432) -> 71680
#define PV_PBUF 71680
#define PV_STAT 143360
#define PV_SMEM_BYTES 144384

__global__ __launch_bounds__(512, 1) void pv_mma_kernel(
    float* __restrict__ attn,
    const __half* __restrict__ VH, const __half* __restrict__ VL) {
    extern __shared__ char smc[];
    uint32_t sb = su32(smc);
    float* msm  = (float*)(smc + PV_STAT);
    float* ilsm = (float*)(smc + PV_STAT + 512);

    int tid = threadIdx.x, lane = tid & 31, w = tid >> 5;
    int g = lane >> 2, tg = lane & 3;
    int wr = w & 7, wc = w >> 3;
    int hb = blockIdx.x, qt = blockIdx.y;

    if (tid < 128) {
        msm[tid] = g_m[hb * SEQ + qt * 128 + tid];
        ilsm[tid] = 1.0f / g_l[hb * SEQ + qt * 128 + tid];
    }
    __syncthreads();

    float* arow = attn + (size_t)hb * SEQ * SEQ + (size_t)(qt * 128) * SEQ;
    size_t vbase = (size_t)(hb * SEQ);
    float C[4][4];
#pragma unroll
    for (int j = 0; j < 4; j++) { C[j][0] = C[j][1] = C[j][2] = C[j][3] = 0.f; }

    // V staging coords: 1024 16B chunks per 128x64-half array, 2 per thread
    int vr0 = tid >> 3, vc0 = (tid & 7) * 8;
    int vr1 = vr0 + 64;
    // A staging coords: thread f covers (r = f>>5, c = (f&31)*4), 8 iters
    float4 aR[8];

    // prologue: chunk 0 -> buf 0
    {
        uint32_t bufc = sb;
        CP16(bufc + 34816 + (vr0 * 72 + vc0) * 2, VH + (vbase + vr0) * DHEAD + vc0);
        CP16(bufc + 34816 + (vr1 * 72 + vc0) * 2, VH + (vbase + vr1) * DHEAD + vc0);
        CP16(bufc + 53248 + (vr0 * 72 + vc0) * 2, VL + (vbase + vr0) * DHEAD + vc0);
        CP16(bufc + 53248 + (vr1 * 72 + vc0) * 2, VL + (vbase + vr1) * DHEAD + vc0);
        CP_COMMIT();
#pragma unroll
        for (int t = 0; t < 8; t++) {
            int f = tid + t * 512;
            int r = f >> 5, c = (f & 31) << 2;
            aR[t] = *(const float4*)(arow + (size_t)r * SEQ + c);
        }
#pragma unroll
        for (int t = 0; t < 8; t++) {
            int f = tid + t * 512;
            int r = f >> 5, c = (f & 31) << 2;
            float4 v = aR[t];
            float mm = msm[r], il = ilsm[r];
            v.x = ex2f(v.x - mm) * il; v.y = ex2f(v.y - mm) * il;
            v.z = ex2f(v.z - mm) * il; v.w = ex2f(v.w - mm) * il;
            *(float4*)(arow + (size_t)r * SEQ + c) = v;
            *(uint2*)(smc + (r * 136 + c) * 2) = h2hi(v);
        }
        CP_WAIT0();
    }
    __syncthreads();

    int arw = wr * 16 + (lane & 15);
    int acl = ((lane >> 4) & 1) * 8;
    int brow4 = (lane & 15);
    int bcol4 = wc * 32 + ((lane >> 4) & 1) * 8;

    for (int kc = 0; kc < 16; kc++) {
        int b = kc & 1;
        if (kc < 15) {
            // issue next V tile + load next A chunk registers
            size_t vb2 = vbase + (size_t)(kc + 1) * 128;
            uint32_t bufn = sb + (b ^ 1) * PV_PBUF;
            CP16(bufn + 34816 + (vr0 * 72 + vc0) * 2, VH + (vb2 + vr0) * DHEAD + vc0);
            CP16(bufn + 34816 + (vr1 * 72 + vc0) * 2, VH + (vb2 + vr1) * DHEAD + vc0);
            CP16(bufn + 53248 + (vr0 * 72 + vc0) * 2, VL + (vb2 + vr0) * DHEAD + vc0);
            CP16(bufn + 53248 + (vr1 * 72 + vc0) * 2, VL + (vb2 + vr1) * DHEAD + vc0);
            CP_COMMIT();
#pragma unroll
            for (int t = 0; t < 8; t++) {
                int f = tid + t * 512;
                int r = f >> 5, c = (f & 31) << 2;
                aR[t] = *(const float4*)(arow + (size_t)r * SEQ + (kc + 1) * 128 + c);
            }
        }
        // mma on current buffer: 8 k-steps of 16 keys
        uint32_t bufb = sb + b * PV_PBUF;
#pragma unroll
        for (int s = 0; s < 8; s++) {
            uint32_t aHf[4];
            uint32_t off = (uint32_t)((arw * 136 + s * 16 + acl) * 2);
            ldmA(aHf, bufb + off);
#pragma unroll
            for (int jp = 0; jp < 2; jp++) {
                uint32_t boff = (uint32_t)(((s * 16 + brow4) * 72 + bcol4 + jp * 16) * 2);
                uint32_t b4H[4], b4L[4];
                ldmB4(b4H, bufb + 34816 + boff);
                ldmB4(b4L, bufb + 53248 + boff);
#pragma unroll
                for (int jj = 0; jj < 2; jj++) {
                    float* Cp = C[jp * 2 + jj];
                    mma_f16(Cp, aHf, b4H + jj * 2);
                    mma_f16(Cp, aHf, b4L + jj * 2);
                }
            }
        }
        if (kc < 15) {
            char* bufc = smc + (b ^ 1) * PV_PBUF;
#pragma unroll
            for (int t = 0; t < 8; t++) {
                int f = tid + t * 512;
                int r = f >> 5, c = (f & 31) << 2;
                float4 v = aR[t];
                float mm = msm[r], il = ilsm[r];
                v.x = ex2f(v.x - mm) * il; v.y = ex2f(v.y - mm) * il;
                v.z = ex2f(v.z - mm) * il; v.w = ex2f(v.w - mm) * il;
                *(float4*)(arow + (size_t)r * SEQ + (kc + 1) * 128 + c) = v;
                *(uint2*)(bufc + (r * 136 + c) * 2) = h2hi(v);
            }
            CP_WAIT0();
        }
        __syncthreads();
    }

    int h = hb >> 1, bb = hb & 1;
    int r1 = wr * 16 + g;
    float* o1 = g_oh + ((size_t)(bb * SEQ + qt * 128 + r1)) * HD + h * 64 + wc * 32 + 2 * tg;
    float* o2 = o1 + 8 * HD;
#pragma unroll
    for (int j = 0; j < 4; j++) {
        *(float2*)(o1 + j * 8) = make_float2(C[j][0], C[j][1]);
        *(float2*)(o2 + j * 8) = make_float2(C[j][2], C[j][3]);
    }
}

// ==================== kernel 4: out projection via f16-2x (unchanged from R16) ====================
#define OP_PBUF 53248
#define OP_SMEM_BYTES 106496

__global__ __launch_bounds__(512, 1) void oproj_mma_kernel(
    const float* __restrict__ Wo, const float* __restrict__ bo, float* __restrict__ out) {
    extern __shared__ char smc[];
    uint32_t sb = su32(smc);

    int tid = threadIdx.x, lane = tid & 31, w = tid >> 5;
    int g = lane >> 2, tg = lane & 3;
    int wr = w & 7, wc = w >> 3;
    int rt = blockIdx.x, ct = blockIdx.y;

    float C[8][4];
#pragma unroll
    for (int j = 0; j < 8; j++) { C[j][0] = C[j][1] = C[j][2] = C[j][3] = 0.f; }

    float4 aR[4], bR[4];
    {
#pragma unroll
        for (int t = 0; t < 4; t++) {
            int f = tid + t * 512;
            int r = f >> 4, c = (f & 15) << 2;
            aR[t] = *(const float4*)(g_oh + (size_t)(rt * 128 + r) * HD + c);
        }
#pragma unroll
        for (int t = 0; t < 4; t++) {
            int f = tid + t * 512;
            int kk = f >> 5, nn = (f & 31) << 2;
            bR[t] = *(const float4*)(Wo + (size_t)kk * DO + ct * 128 + nn);
        }
        char* bufc = smc;
#pragma unroll
        for (int t = 0; t < 4; t++) {
            int f = tid + t * 512;
            int r = f >> 4, c = (f & 15) << 2;
            *(uint2*)(bufc + (r * 72 + c) * 2) = h2hi(aR[t]);
        }
#pragma unroll
        for (int t = 0; t < 4; t++) {
            int f = tid + t * 512;
            int kk = f >> 5, nn = (f & 31) << 2;
            uint2 hp, lp;
            h2split(bR[t], hp, lp);
            *(uint2*)(bufc + 18432 + (kk * 136 + nn) * 2) = hp;
            *(uint2*)(bufc + 35840 + (kk * 136 + nn) * 2) = lp;
        }
    }
    __syncthreads();

    int arw = wr * 16 + (lane & 15);
    int acl = ((lane >> 4) & 1) * 8;
    int brow4 = (lane & 15);
    int bcol4 = wc * 64 + ((lane >> 4) & 1) * 8;

    for (int kc = 0; kc < 16; kc++) {
        int b = kc & 1;
        if (kc < 15) {
#pragma unroll
            for (int t = 0; t < 4; t++) {
                int f = tid + t * 512;
                int r = f >> 4, c = (f & 15) << 2;
                aR[t] = *(const float4*)(g_oh + (size_t)(rt * 128 + r) * HD + (kc + 1) * 64 + c);
            }
#pragma unroll
            for (int t = 0; t < 4; t++) {
                int f = tid + t * 512;
                int kk = f >> 5, nn = (f & 31) << 2;
                bR[t] = *(const float4*)(Wo + (size_t)((kc + 1) * 64 + kk) * DO + ct * 128 + nn);
            }
        }
        uint32_t bufb = sb + b * OP_PBUF;
        uint32_t aHf[4][4];
#pragma unroll
        for (int s = 0; s < 4; s++) {
            uint32_t off = (uint32_t)((arw * 72 + s * 16 + acl) * 2);
            ldmA(aHf[s], bufb + off);
        }
#pragma unroll
        for (int jp = 0; jp < 4; jp++) {
#pragma unroll
            for (int s = 0; s < 4; s++) {
                uint32_t boff = (uint32_t)(((s * 16 + brow4) * 136 + bcol4 + jp * 16) * 2);
                uint32_t b4H[4], b4L[4];
                ldmB4(b4H, bufb + 18432 + boff);
                ldmB4(b4L, bufb + 35840 + boff);
#pragma unroll
                for (int jj = 0; jj < 2; jj++) {
                    float* Cp = C[jp * 2 + jj];
                    mma_f16(Cp, aHf[s], b4H + jj * 2);
                    mma_f16(Cp, aHf[s], b4L + jj * 2);
                }
            }
        }
        if (kc < 15) {
            char* bufc = smc + (b ^ 1) * OP_PBUF;
#pragma unroll
            for (int t = 0; t < 4; t++) {
                int f = tid + t * 512;
                int r = f >> 4, c = (f & 15) << 2;
                *(uint2*)(bufc + (r * 72 + c) * 2) = h2hi(aR[t]);
            }
#pragma unroll
            for (int t = 0; t < 4; t++) {
                int f = tid + t * 512;
                int kk = f >> 5, nn = (f & 31) << 2;
                uint2 hp, lp;
                h2split(bR[t], hp, lp);
                *(uint2*)(bufc + 18432 + (kk * 136 + nn) * 2) = hp;
                *(uint2*)(bufc + 35840 + (kk * 136 + nn) * 2) = lp;
            }
        }
        __syncthreads();
    }

    int r1 = wr * 16 + g;
    const float* bp = bo + ct * 128 + wc * 64;
    float* o1 = out + (size_t)(rt * 128 + r1) * DO + ct * 128 + wc * 64 + 2 * tg;
    float* o2 = o1 + 8 * DO;
#pragma unroll
    for (int j = 0; j < 8; j++) {
        int cc = j * 8 + 2 * tg;
        *(float2*)(o1 + j * 8) = make_float2(C[j][0] + bp[cc], C[j][1] + bp[cc + 1]);
        *(float2*)(o2 + j * 8) = make_float2(C[j][2] + bp[cc], C[j][3] + bp[cc + 1]);
    }
}

// ==================== launch ====================
extern "C" void kernel_launch(void* const* d_in, const int* in_sizes, int n_in,
                              void* d_out, int out_size) {
    const float* q  = (const float*)d_in[0];
    const float* k  = (const float*)d_in[1];
    const float* v  = (const float*)d_in[2];
    const float* Wq = (const float*)d_in[3];
    const float* bq = (const float*)d_in[4];
    const float* Wk = (const float*)d_in[5];
    const float* bk = (const float*)d_in[6];
    const float* Wv = (const float*)d_in[7];
    const float* bv = (const float*)d_in[8];
    const float* Wo = (const float*)d_in[9];
    const float* bo = (const float*)d_in[10];
    (void)in_sizes; (void)n_in;

    long long osz = (long long)out_size;
    float* attn = nullptr;
    float* out  = nullptr;
    if (osz >= ATTN_ELEMS + OUT_ELEMS) {
        attn = (float*)d_out;
        out  = (float*)d_out + ATTN_ELEMS;
    } else if (osz >= ATTN_ELEMS) {
        attn = (float*)d_out;
    } else {
        out = (float*)d_out;
    }
    if (!attn) cudaGetSymbolAddress((void**)&attn, g_attn_fb);

    __half *QH, *QL, *KH, *KL, *VH, *VL;
    cudaGetSymbolAddress((void**)&QH, g_QHh);
    cudaGetSymbolAddress((void**)&QL, g_QLh);
    cudaGetSymbolAddress((void**)&KH, g_KHh);
    cudaGetSymbolAddress((void**)&KL, g_KLh);
    cudaGetSymbolAddress((void**)&VH, g_VHh);
    cudaGetSymbolAddress((void**)&VL, g_VLh);

    cudaFuncSetAttribute(scores_mma_kernel, cudaFuncAttributeMaxDynamicSharedMemorySize, SC_SMEM_BYTES);
    cudaFuncSetAttribute(pv_mma_kernel, cudaFuncAttributeMaxDynamicSharedMemorySize, PV_SMEM_BYTES);
    cudaFuncSetAttribute(oproj_mma_kernel, cudaFuncAttributeMaxDynamicSharedMemorySize, OP_SMEM_BYTES);

    proj_fused_kernel<<<dim3(64, 16, 3), 256>>>(q, k, v, Wq, bq, Wk, bk, Wv, bv,
                                                QH, QL, KH, KL, VH, VL);
    scores_mma_kernel<<<dim3(HB, 16), 512, SC_SMEM_BYTES>>>(attn, QH, QL, KH, KL);
    pv_mma_kernel<<<dim3(HB, 16), 512, PV_SMEM_BYTES>>>(attn, VH, VL);
    if (out) oproj_mma_kernel<<<dim3(32, 8), 512, OP_SMEM_BYTES>>>(Wo, bo, out);
}